// round 4
// baseline (speedup 1.0000x reference)
#include <cuda_runtime.h>
#include <cstdint>

// Problem constants
#define NTOK (512 * 2048)   // 1,048,576 tokens
#define DIN  20
#define DH   256
#define DOUT 10

#define TPB  256            // threads per block
#define TPT  4              // tokens per thread (2 packed pairs)
#define TOKS_PER_BLOCK (TPB * TPT)          // 1024
#define NBLK (NTOK / TOKS_PER_BLOCK)        // 1024 blocks exactly cover all tokens

// Shared: per hidden unit j, 32 x 8B slots = 256B:
//   [0:20)  (W1[i][j], W1[i][j]) packed pairs
//   [20:25) (W2[j][2q], W2[j][2q+1]) packed pairs
//   [25]    (b1[j], b1[j]) packed pair
#define ROWQ 32
#define SMEM_BYTES (DH * ROWQ * 8 + 16 * 8)   // + small b2 area

// Deterministic reduction scratch (no device allocs allowed)
__device__ float g_psy[NBLK];
__device__ float g_psa[NBLK];

// ---------------------------------------------------------------------------
// f32x2 packed-math helpers (Blackwell FFMA2 — only reachable via PTX)
// ---------------------------------------------------------------------------
__device__ __forceinline__ uint64_t pack2(float lo, float hi) {
    uint64_t r;
    asm("mov.b64 %0, {%1, %2};" : "=l"(r) : "f"(lo), "f"(hi));
    return r;
}
__device__ __forceinline__ void unpack2(uint64_t v, float& lo, float& hi) {
    asm("mov.b64 {%0, %1}, %2;" : "=f"(lo), "=f"(hi) : "l"(v));
}
__device__ __forceinline__ void fma2(uint64_t& d, uint64_t a, uint64_t b) {
    asm("fma.rn.f32x2 %0, %1, %2, %0;" : "+l"(d) : "l"(a), "l"(b));
}

// ---------------------------------------------------------------------------
// Kernel 1: fused MLP (packed f32x2) + per-block (sum y, sum |y|) partials
// ---------------------------------------------------------------------------
__global__ __launch_bounds__(TPB, 1)
void mlp_main(const float* __restrict__ X,
              const float* __restrict__ W1,   // [DIN, DH] row-major
              const float* __restrict__ b1,   // [DH]
              const float* __restrict__ W2,   // [DH, DOUT] row-major
              const float* __restrict__ b2)   // [DOUT]
{
    extern __shared__ uint64_t wsh[];              // DH*ROWQ pairs + b2
    float* b2sh = reinterpret_cast<float*>(wsh + DH * ROWQ);

    const int tid = threadIdx.x;

    // Init packed weight rows
    for (int j = tid; j < DH; j += TPB) {
        uint64_t* row = &wsh[j * ROWQ];
        #pragma unroll
        for (int i = 0; i < DIN; ++i) {
            float w = W1[i * DH + j];
            row[i] = pack2(w, w);
        }
        #pragma unroll
        for (int q = 0; q < DOUT / 2; ++q)
            row[DIN + q] = pack2(W2[j * DOUT + 2 * q], W2[j * DOUT + 2 * q + 1]);
        float bb = b1[j];
        row[25] = pack2(bb, bb);
    }
    if (tid < DOUT) b2sh[tid] = b2[tid];
    __syncthreads();

    // Load 4 tokens, pack as 2 pairs: x2[p][i] = (x[2p][i], x[2p+1][i])
    const long base = (long)blockIdx.x * TOKS_PER_BLOCK;
    float xs[TPT][DIN];
    #pragma unroll
    for (int t = 0; t < TPT; ++t) {
        const long tok = base + (long)t * TPB + tid;
        const float4* p = reinterpret_cast<const float4*>(X + tok * DIN);
        #pragma unroll
        for (int q = 0; q < DIN / 4; ++q) {
            float4 v = p[q];
            xs[t][4 * q + 0] = v.x;
            xs[t][4 * q + 1] = v.y;
            xs[t][4 * q + 2] = v.z;
            xs[t][4 * q + 3] = v.w;
        }
    }
    uint64_t x2[2][DIN];
    #pragma unroll
    for (int p = 0; p < 2; ++p)
        #pragma unroll
        for (int i = 0; i < DIN; ++i)
            x2[p][i] = pack2(xs[2 * p][i], xs[2 * p + 1][i]);

    // Accumulators: acc2[t][q] = (y[t][2q], y[t][2q+1])
    uint64_t acc2[TPT][DOUT / 2];
    const uint64_t zz = pack2(0.0f, 0.0f);
    #pragma unroll
    for (int t = 0; t < TPT; ++t)
        #pragma unroll
        for (int q = 0; q < DOUT / 2; ++q) acc2[t][q] = zz;

    // Main loop over hidden units, unrolled x2 for two independent LDS->FMA chains.
    #pragma unroll 1
    for (int jj = 0; jj < DH; jj += 2) {
        #pragma unroll
        for (int u = 0; u < 2; ++u) {
            const int j = jj + u;
            const uint64_t* row = &wsh[j * ROWQ];

            // 13 x LDS.128 (broadcast, conflict-free): 20 w1 pairs, 5 w2 pairs, b1 pair
            uint64_t w1p[DIN], w2p[DOUT / 2], b1p;
            #pragma unroll
            for (int q = 0; q < DIN / 2; ++q) {
                ulonglong2 v = reinterpret_cast<const ulonglong2*>(row)[q];
                w1p[2 * q] = v.x; w1p[2 * q + 1] = v.y;
            }
            {
                ulonglong2 v0 = reinterpret_cast<const ulonglong2*>(row)[10];
                ulonglong2 v1 = reinterpret_cast<const ulonglong2*>(row)[11];
                ulonglong2 v2 = reinterpret_cast<const ulonglong2*>(row)[12];
                w2p[0] = v0.x; w2p[1] = v0.y; w2p[2] = v1.x; w2p[3] = v1.y;
                w2p[4] = v2.x; b1p = v2.y;
            }

            // Layer 1: h pairs (token-packed), 20 FFMA2 per pair
            uint64_t h2[2] = { b1p, b1p };
            #pragma unroll
            for (int i = 0; i < DIN; ++i) {
                fma2(h2[0], x2[0][i], w1p[i]);
                fma2(h2[1], x2[1][i], w1p[i]);
            }

            // ReLU + broadcast-pack h per token
            float h0, h1, h2f, h3;
            unpack2(h2[0], h0, h1);
            unpack2(h2[1], h2f, h3);
            h0 = fmaxf(h0, 0.0f); h1 = fmaxf(h1, 0.0f);
            h2f = fmaxf(h2f, 0.0f); h3 = fmaxf(h3, 0.0f);
            uint64_t hb[TPT] = { pack2(h0, h0), pack2(h1, h1),
                                 pack2(h2f, h2f), pack2(h3, h3) };

            // Layer 2: 5 FFMA2 per token (output-packed)
            #pragma unroll
            for (int t = 0; t < TPT; ++t)
                #pragma unroll
                for (int q = 0; q < DOUT / 2; ++q)
                    fma2(acc2[t][q], hb[t], w2p[q]);
        }
    }

    // Per-thread epilogue: add b2, accumulate sum(y) and sum(|y|)
    float sy = 0.0f, sa = 0.0f;
    #pragma unroll
    for (int t = 0; t < TPT; ++t) {
        #pragma unroll
        for (int q = 0; q < DOUT / 2; ++q) {
            float ya, yb;
            unpack2(acc2[t][q], ya, yb);
            ya += b2sh[2 * q];
            yb += b2sh[2 * q + 1];
            sy += ya + yb;
            sa += fabsf(ya) + fabsf(yb);
        }
    }

    // Block reduction (deterministic): warp shuffles + shared
    const int lane = tid & 31;
    const int wid  = tid >> 5;
    #pragma unroll
    for (int off = 16; off > 0; off >>= 1) {
        sy += __shfl_down_sync(0xFFFFFFFFu, sy, off);
        sa += __shfl_down_sync(0xFFFFFFFFu, sa, off);
    }
    __shared__ float rsy[TPB / 32];
    __shared__ float rsa[TPB / 32];
    if (lane == 0) { rsy[wid] = sy; rsa[wid] = sa; }
    __syncthreads();
    if (wid == 0) {
        sy = (lane < TPB / 32) ? rsy[lane] : 0.0f;
        sa = (lane < TPB / 32) ? rsa[lane] : 0.0f;
        #pragma unroll
        for (int off = 4; off > 0; off >>= 1) {
            sy += __shfl_down_sync(0xFFFFFFFFu, sy, off);
            sa += __shfl_down_sync(0xFFFFFFFFu, sa, off);
        }
        if (lane == 0) {
            g_psy[blockIdx.x] = sy;
            g_psa[blockIdx.x] = sa;
        }
    }
}

// ---------------------------------------------------------------------------
// Kernel 2: final reduce (double precision) + halving-count scale
// ---------------------------------------------------------------------------
__global__ __launch_bounds__(TPB)
void mlp_finalize(float* __restrict__ out)
{
    const int tid = threadIdx.x;
    double sy = 0.0, sa = 0.0;
    for (int i = tid; i < NBLK; i += TPB) {
        sy += (double)g_psy[i];
        sa += (double)g_psa[i];
    }
    const int lane = tid & 31;
    const int wid  = tid >> 5;
    #pragma unroll
    for (int off = 16; off > 0; off >>= 1) {
        sy += __shfl_down_sync(0xFFFFFFFFu, sy, off);
        sa += __shfl_down_sync(0xFFFFFFFFu, sa, off);
    }
    __shared__ double dsy[TPB / 32];
    __shared__ double dsa[TPB / 32];
    if (lane == 0) { dsy[wid] = sy; dsa[wid] = sa; }
    __syncthreads();
    if (tid == 0) {
        double tsy = 0.0, tsa = 0.0;
        #pragma unroll
        for (int w = 0; w < TPB / 32; ++w) { tsy += dsy[w]; tsa += dsa[w]; }
        // Replicate: while s > 1: s /= 2; n++;  then out = sum(y) * 2^-n
        int n = 0;
        double s = tsa;
        while (s > 1.0) { s *= 0.5; ++n; }
        out[0] = (float)ldexp(tsy, -n);
    }
}

// ---------------------------------------------------------------------------
// Launch contract
// ---------------------------------------------------------------------------
extern "C" void kernel_launch(void* const* d_in, const int* in_sizes, int n_in,
                              void* d_out, int out_size)
{
    const float* X  = (const float*)d_in[0];
    const float* W1 = (const float*)d_in[1];
    const float* b1 = (const float*)d_in[2];
    const float* W2 = (const float*)d_in[3];
    const float* b2 = (const float*)d_in[4];
    float* out = (float*)d_out;

    cudaFuncSetAttribute(mlp_main, cudaFuncAttributeMaxDynamicSharedMemorySize, SMEM_BYTES);
    mlp_main<<<NBLK, TPB, SMEM_BYTES>>>(X, W1, b1, W2, b2);
    mlp_finalize<<<1, TPB>>>(out);
}

// round 6
// speedup vs baseline: 2.3079x; 2.3079x over previous
#include <cuda_runtime.h>
#include <cstdint>

// ---------------------------------------------------------------------------
// Problem constants
// ---------------------------------------------------------------------------
#define NTOK (512 * 2048)     // 1,048,576 tokens
#define DIN  20
#define DH   256
#define DOUT 10

#define TPB      256          // 8 warps
#define WARPS    8
#define TW       4            // 16-token tiles per warp
#define TILE_TOK 16
#define NTILES   (NTOK / TILE_TOK)                 // 65536
#define NBLK     (NTILES / (WARPS * TW))           // 2048

// Shared layout (in floats, dynamic)
#define W1F_OFF 0                         // 96 tiles * 64 = 6144
#define W2F_OFF 6144                      // 64 tiles * 64 = 4096
#define B1P_OFF 10240                     // 32 n-tiles * 8  = 256
#define B2_OFF  10496                     // 16
#define XS_OFF  10512                     // 8 warps * 16*25 = 3200
#define SMEM_FLOATS (XS_OFF + WARPS * 16 * 25)     // 13712
#define SMEM_BYTES  (SMEM_FLOATS * 4)              // 54848

// Reduction scratch
__device__ float g_psy[NBLK];
__device__ float g_psa[NBLK];

// ---------------------------------------------------------------------------
// Helpers
// ---------------------------------------------------------------------------
__device__ __forceinline__ float tf32r(float x) {
    uint32_t u;
    asm("cvt.rna.tf32.f32 %0, %1;" : "=r"(u) : "f"(x));
    return __uint_as_float(u);
}

// mma.sync m16n8k8 tf32: D += A*B (D,C same regs)
__device__ __forceinline__ void mma8(float& d0, float& d1, float& d2, float& d3,
                                     float a0, float a1, float a2, float a3,
                                     float b0, float b1) {
    asm volatile(
        "mma.sync.aligned.m16n8k8.row.col.f32.tf32.tf32.f32 "
        "{%0,%1,%2,%3}, {%4,%5,%6,%7}, {%8,%9}, {%0,%1,%2,%3};\n"
        : "+f"(d0), "+f"(d1), "+f"(d2), "+f"(d3)
        : "r"(__float_as_uint(a0)), "r"(__float_as_uint(a1)),
          "r"(__float_as_uint(a2)), "r"(__float_as_uint(a3)),
          "r"(__float_as_uint(b0)), "r"(__float_as_uint(b1)));
}

// ---------------------------------------------------------------------------
// Kernel 1: fused two-GEMM MLP via mma.sync tf32 + per-block partial sums
// ---------------------------------------------------------------------------
__global__ __launch_bounds__(TPB, 2)
void mlp_main(const float* __restrict__ X,
              const float* __restrict__ W1,   // [DIN, DH]
              const float* __restrict__ b1,   // [DH]
              const float* __restrict__ W2,   // [DH, DOUT]
              const float* __restrict__ b2)   // [DOUT]
{
    extern __shared__ float sm[];
    const int tid  = threadIdx.x;
    const int lane = tid & 31;
    const int warp = tid >> 5;
    const int g    = lane >> 2;    // group row 0..7
    const int t    = lane & 3;     // thread-in-group 0..3

    // ---- Build W1 B-frags (with hidden permutation), K padded 20->24 ----
    // tile = n*3 + k ; value at (lane,r): row = k*8 + (lane&3) + r*4 (K index)
    // physical col p = lane>>2 ; logical hidden l = (p&1) ? (p>>1)+4 : (p>>1)
    for (int idx = tid; idx < 96 * 64; idx += TPB) {
        int tile = idx >> 6, pos = idx & 63;
        int ln = pos >> 1, r = pos & 1;
        int n = tile / 3, k = tile - 3 * n;
        int row = k * 8 + (ln & 3) + r * 4;
        int p = ln >> 2;
        int l = (p & 1) ? (p >> 1) + 4 : (p >> 1);
        float v = (row < DIN) ? W1[row * DH + n * 8 + l] : 0.0f;
        sm[W1F_OFF + idx] = tf32r(v);
    }
    // ---- W2 B-frags: tile = kc*2 + n2 ; no permutation (logical rows) ----
    for (int idx = tid; idx < 64 * 64; idx += TPB) {
        int tile = idx >> 6, pos = idx & 63;
        int ln = pos >> 1, r = pos & 1;
        int kc = tile >> 1, n2 = tile & 1;
        int row = kc * 8 + (ln & 3) + r * 4;      // hidden (logical)
        int col = n2 * 8 + (ln >> 2);             // output, padded
        float v = (col < DOUT) ? W2[row * DOUT + col] : 0.0f;
        sm[W2F_OFF + idx] = tf32r(v);
    }
    // ---- b1 pairs: b1p[n][t] = (b1[n*8+t], b1[n*8+t+4]) ----
    for (int idx = tid; idx < 32 * 8; idx += TPB) {
        int n = idx >> 3, q = idx & 7;
        int tt = q >> 1, hi = q & 1;
        sm[B1P_OFF + idx] = b1[n * 8 + tt + (hi ? 4 : 0)];
    }
    // ---- b2 padded ----
    if (tid < 16) sm[B2_OFF + tid] = (tid < DOUT) ? b2[tid] : 0.0f;
    // ---- zero X staging (cols 20..24 stay zero forever) ----
    for (int idx = tid; idx < WARPS * 16 * 25; idx += TPB)
        sm[XS_OFF + idx] = 0.0f;
    __syncthreads();

    const float b2v0 = sm[B2_OFF + 2 * t];
    const float b2v1 = sm[B2_OFF + 2 * t + 1];
    const float b2v2 = sm[B2_OFF + 2 * t + 8];
    const float b2v3 = sm[B2_OFF + 2 * t + 9];

    float* xs = &sm[XS_OFF + warp * (16 * 25)];

    float sy = 0.0f, sa = 0.0f;

    #pragma unroll 1
    for (int it = 0; it < TW; ++it) {
        const int tile_id = (blockIdx.x * WARPS + warp) * TW + it;
        const size_t tok0 = (size_t)tile_id * TILE_TOK;

        // Guard: no lane may still be reading xs from the previous iteration
        __syncwarp();

        // ---- Stage X tile: 320 floats, rna-rounded, rows padded to 25 ----
        const float* xg = X + tok0 * DIN;
        #pragma unroll
        for (int i = 0; i < 10; ++i) {
            int f = lane + 32 * i;           // 0..319
            int tok = f / DIN;
            int c = f - tok * DIN;
            xs[tok * 25 + c] = tf32r(xg[f]);
        }
        __syncwarp();

        // ---- A-frags for GEMM1 (3 k-steps) ----
        float a[3][4];
        #pragma unroll
        for (int k = 0; k < 3; ++k) {
            int c0 = t + 8 * k;
            a[k][0] = xs[g * 25 + c0];
            a[k][1] = xs[(g + 8) * 25 + c0];
            a[k][2] = xs[g * 25 + c0 + 4];
            a[k][3] = xs[(g + 8) * 25 + c0 + 4];
        }

        float y0[4] = {0.f, 0.f, 0.f, 0.f};
        float y1[4] = {0.f, 0.f, 0.f, 0.f};

        #pragma unroll
        for (int c = 0; c < 4; ++c) {
            float hc[8][4];

            // GEMM1 for this chunk: 8 n-tiles x 3 k-steps
            #pragma unroll
            for (int nt = 0; nt < 8; ++nt) {
                const int n = c * 8 + nt;
                float d0 = 0.f, d1 = 0.f, d2 = 0.f, d3 = 0.f;
                #pragma unroll
                for (int k = 0; k < 3; ++k) {
                    const float2 b = *reinterpret_cast<const float2*>(
                        &sm[W1F_OFF + (n * 3 + k) * 64 + lane * 2]);
                    mma8(d0, d1, d2, d3,
                         a[k][0], a[k][1], a[k][2], a[k][3], b.x, b.y);
                }
                // bias + relu + tf32 round  (C-frag == A2-frag via hidden perm)
                const float2 bp = *reinterpret_cast<const float2*>(
                    &sm[B1P_OFF + n * 8 + t * 2]);
                hc[nt][0] = tf32r(fmaxf(d0 + bp.x, 0.0f));
                hc[nt][1] = tf32r(fmaxf(d1 + bp.y, 0.0f));
                hc[nt][2] = tf32r(fmaxf(d2 + bp.x, 0.0f));
                hc[nt][3] = tf32r(fmaxf(d3 + bp.y, 0.0f));
            }

            // GEMM2 for this chunk: 8 k-steps x 2 n-tiles
            // A2 frag = (c0, c2, c1, c3) of the GEMM1 accumulator
            #pragma unroll
            for (int nt = 0; nt < 8; ++nt) {
                const int kc = c * 8 + nt;
                const float2 bA = *reinterpret_cast<const float2*>(
                    &sm[W2F_OFF + (kc * 2 + 0) * 64 + lane * 2]);
                mma8(y0[0], y0[1], y0[2], y0[3],
                     hc[nt][0], hc[nt][2], hc[nt][1], hc[nt][3], bA.x, bA.y);
                const float2 bB = *reinterpret_cast<const float2*>(
                    &sm[W2F_OFF + (kc * 2 + 1) * 64 + lane * 2]);
                mma8(y1[0], y1[1], y1[2], y1[3],
                     hc[nt][0], hc[nt][2], hc[nt][1], hc[nt][3], bB.x, bB.y);
            }
        }

        // ---- Epilogue 2: y += b2 ; accumulate sums (pad cols are exact 0) ----
        {
            float v;
            v = y0[0] + b2v0; sy += v; sa += fabsf(v);
            v = y0[1] + b2v1; sy += v; sa += fabsf(v);
            v = y0[2] + b2v0; sy += v; sa += fabsf(v);
            v = y0[3] + b2v1; sy += v; sa += fabsf(v);
            v = y1[0] + b2v2; sy += v; sa += fabsf(v);
            v = y1[1] + b2v3; sy += v; sa += fabsf(v);
            v = y1[2] + b2v2; sy += v; sa += fabsf(v);
            v = y1[3] + b2v3; sy += v; sa += fabsf(v);
        }
    }

    // ---- Block reduction -> per-block partials ----
    #pragma unroll
    for (int off = 16; off > 0; off >>= 1) {
        sy += __shfl_down_sync(0xFFFFFFFFu, sy, off);
        sa += __shfl_down_sync(0xFFFFFFFFu, sa, off);
    }
    __shared__ float rsy[WARPS], rsa[WARPS];
    if (lane == 0) { rsy[warp] = sy; rsa[warp] = sa; }
    __syncthreads();
    if (tid == 0) {
        float tsy = 0.f, tsa = 0.f;
        #pragma unroll
        for (int w = 0; w < WARPS; ++w) { tsy += rsy[w]; tsa += rsa[w]; }
        g_psy[blockIdx.x] = tsy;
        g_psa[blockIdx.x] = tsa;
    }
}

// ---------------------------------------------------------------------------
// Kernel 2: final reduce (double precision) + exact halving-count scale
// ---------------------------------------------------------------------------
__global__ __launch_bounds__(256)
void mlp_finalize(float* __restrict__ out)
{
    const int tid = threadIdx.x;
    double sy = 0.0, sa = 0.0;
    for (int i = tid; i < NBLK; i += 256) {
        sy += (double)g_psy[i];
        sa += (double)g_psa[i];
    }
    const int lane = tid & 31;
    const int wid  = tid >> 5;
    #pragma unroll
    for (int off = 16; off > 0; off >>= 1) {
        sy += __shfl_down_sync(0xFFFFFFFFu, sy, off);
        sa += __shfl_down_sync(0xFFFFFFFFu, sa, off);
    }
    __shared__ double dsy[8], dsa[8];
    if (lane == 0) { dsy[wid] = sy; dsa[wid] = sa; }
    __syncthreads();
    if (tid == 0) {
        double tsy = 0.0, tsa = 0.0;
        #pragma unroll
        for (int w = 0; w < 8; ++w) { tsy += dsy[w]; tsa += dsa[w]; }
        int n = 0;
        double s = tsa;
        while (s > 1.0) { s *= 0.5; ++n; }
        out[0] = (float)ldexp(tsy, -n);
    }
}

// ---------------------------------------------------------------------------
// Launch contract
// ---------------------------------------------------------------------------
extern "C" void kernel_launch(void* const* d_in, const int* in_sizes, int n_in,
                              void* d_out, int out_size)
{
    const float* X  = (const float*)d_in[0];
    const float* W1 = (const float*)d_in[1];
    const float* b1 = (const float*)d_in[2];
    const float* W2 = (const float*)d_in[3];
    const float* b2 = (const float*)d_in[4];
    float* out = (float*)d_out;

    cudaFuncSetAttribute(mlp_main, cudaFuncAttributeMaxDynamicSharedMemorySize, SMEM_BYTES);
    mlp_main<<<NBLK, TPB, SMEM_BYTES>>>(X, W1, b1, W2, b2);
    mlp_finalize<<<1, 256>>>(out);
}